// round 3
// baseline (speedup 1.0000x reference)
#include <cuda_runtime.h>
#include <cstdint>

#define N_NODES 100000
#define N_EDGES 20000
#define NNZ     1000000
#define IN_CH   128
#define OUT_DIM 64

// Scratch (device globals: allocation-free per harness rules).
// 16B alignment required for red.global.add.v4.f32 targets.
__device__ __align__(16) float g_Xl[(size_t)N_NODES * OUT_DIM];  // 25.6 MB
__device__ __align__(16) float g_Xe[(size_t)N_EDGES * OUT_DIM];  // 5.12 MB

// ---------------------------------------------------------------------------
// Vector reduction: red.global.add.v4.f32 (sm_90+), no return value.
// ---------------------------------------------------------------------------
__device__ __forceinline__ void red_add_v4(float* addr, float4 v) {
    asm volatile("red.global.add.v4.f32 [%0], {%1, %2, %3, %4};"
                 :: "l"(addr), "f"(v.x), "f"(v.y), "f"(v.z), "f"(v.w)
                 : "memory");
}

// ---------------------------------------------------------------------------
// Zero g_Xe and d_out (d_out is poisoned 0xAA by the harness)
// ---------------------------------------------------------------------------
__global__ void k_zero(float* __restrict__ out) {
    int t = blockIdx.x * blockDim.x + threadIdx.x;
    if (t < N_EDGES * OUT_DIM) g_Xe[t] = 0.0f;
    if (t < N_NODES * OUT_DIM) out[t] = 0.0f;
}

// ---------------------------------------------------------------------------
// GEMM: g_Xl[N,64] = X[N,128] @ W[128,64]
// Block: 256 threads, tile 64 rows x 64 cols, 4x4 register micro-tile.
// W fully staged in smem (32KB); X staged transposed [k][row] in 32-k chunks.
// ---------------------------------------------------------------------------
__global__ __launch_bounds__(256) void k_gemm(const float* __restrict__ X,
                                              const float* __restrict__ W) {
    __shared__ float Ws[IN_CH][OUT_DIM];  // [k][col], 32 KB
    __shared__ float Xs[32][68];          // [k][row], padded to kill bank conflicts

    const int tid  = threadIdx.x;
    const int row0 = blockIdx.x * 64;

    // Stage all of W (8192 floats = 2048 float4)
    {
        const float4* W4  = (const float4*)W;
        float4*       Ws4 = (float4*)&Ws[0][0];
        #pragma unroll
        for (int i = tid; i < IN_CH * OUT_DIM / 4; i += 256) Ws4[i] = W4[i];
    }

    const int tx = tid & 15;   // col group: cols 4*tx .. 4*tx+3
    const int ty = tid >> 4;   // row group: rows 4*ty .. 4*ty+3

    float acc[4][4];
    #pragma unroll
    for (int i = 0; i < 4; ++i)
        #pragma unroll
        for (int j = 0; j < 4; ++j) acc[i][j] = 0.0f;

    const int lr  = tid >> 3;  // 0..31: base row for staging
    const int lkf = tid & 7;   // 0..7: float4 index within 32-k chunk

    for (int kc = 0; kc < 4; ++kc) {
        __syncthreads();
        // Stage X chunk transposed: Xs[k_local][row]
        #pragma unroll
        for (int j = 0; j < 2; ++j) {
            int r    = lr + 32 * j;
            int grow = row0 + r;
            float4 x = make_float4(0.f, 0.f, 0.f, 0.f);
            if (grow < N_NODES)
                x = *(const float4*)(X + (size_t)grow * IN_CH + kc * 32 + lkf * 4);
            Xs[lkf * 4 + 0][r] = x.x;
            Xs[lkf * 4 + 1][r] = x.y;
            Xs[lkf * 4 + 2][r] = x.z;
            Xs[lkf * 4 + 3][r] = x.w;
        }
        __syncthreads();

        #pragma unroll
        for (int k = 0; k < 32; ++k) {
            float4 a = *(const float4*)&Xs[k][4 * ty];
            float4 b = *(const float4*)&Ws[kc * 32 + k][4 * tx];
            acc[0][0] += a.x * b.x; acc[0][1] += a.x * b.y;
            acc[0][2] += a.x * b.z; acc[0][3] += a.x * b.w;
            acc[1][0] += a.y * b.x; acc[1][1] += a.y * b.y;
            acc[1][2] += a.y * b.z; acc[1][3] += a.y * b.w;
            acc[2][0] += a.z * b.x; acc[2][1] += a.z * b.y;
            acc[2][2] += a.z * b.z; acc[2][3] += a.z * b.w;
            acc[3][0] += a.w * b.x; acc[3][1] += a.w * b.y;
            acc[3][2] += a.w * b.z; acc[3][3] += a.w * b.w;
        }
    }

    #pragma unroll
    for (int i = 0; i < 4; ++i) {
        int grow = row0 + 4 * ty + i;
        if (grow < N_NODES) {
            float4 o = make_float4(acc[i][0], acc[i][1], acc[i][2], acc[i][3]);
            *(float4*)(g_Xl + (size_t)grow * OUT_DIM + 4 * tx) = o;
        }
    }
}

// ---------------------------------------------------------------------------
// Scatter 1: Xe[e] += Xl[v] for every incidence (v, e).
// 16 threads per incidence, one float4 gather + one red.v4 each.
// NOTE: indices are int32 (JAX default; x64 disabled in reference runtime).
// ---------------------------------------------------------------------------
__global__ __launch_bounds__(256) void k_scatterA(const int* __restrict__ vertex,
                                                  const int* __restrict__ edges) {
    int t = blockIdx.x * blockDim.x + threadIdx.x;
    int i = t >> 4;
    if (i >= NNZ) return;
    int c = (t & 15) << 2;
    int v = vertex[i];
    int e = edges[i];
    float4 val = *(const float4*)(g_Xl + (size_t)v * OUT_DIM + c);
    red_add_v4(g_Xe + (size_t)e * OUT_DIM + c, val);
}

// ---------------------------------------------------------------------------
// Scatter 2: out[v] += Xe[e] * (degE[e] * W_edge[e] * degV[v]).
// All three row-scalings folded into the gather (linear, per-row).
// ---------------------------------------------------------------------------
__global__ __launch_bounds__(256) void k_scatterB(const int* __restrict__ vertex,
                                                  const int* __restrict__ edges,
                                                  const float* __restrict__ degE,
                                                  const float* __restrict__ degV,
                                                  const float* __restrict__ W_edge,
                                                  float* __restrict__ out) {
    int t = blockIdx.x * blockDim.x + threadIdx.x;
    int i = t >> 4;
    if (i >= NNZ) return;
    int c = (t & 15) << 2;
    int v = vertex[i];
    int e = edges[i];
    float s = degE[e] * W_edge[e] * degV[v];
    float4 x = *(const float4*)(g_Xe + (size_t)e * OUT_DIM + c);
    x.x *= s; x.y *= s; x.z *= s; x.w *= s;
    red_add_v4(out + (size_t)v * OUT_DIM + c, x);
}

// ---------------------------------------------------------------------------
extern "C" void kernel_launch(void* const* d_in, const int* in_sizes, int n_in,
                              void* d_out, int out_size) {
    const float* X      = (const float*)d_in[0];
    const int*   vertex = (const int*)d_in[1];
    const int*   edges  = (const int*)d_in[2];
    const float* W_lin  = (const float*)d_in[3];
    const float* degE   = (const float*)d_in[4];
    const float* degV   = (const float*)d_in[5];
    const float* W_edge = (const float*)d_in[6];
    float*       out    = (float*)d_out;

    k_zero<<<(N_NODES * OUT_DIM + 255) / 256, 256>>>(out);
    k_gemm<<<(N_NODES + 63) / 64, 256>>>(X, W_lin);
    k_scatterA<<<(NNZ * 16) / 256, 256>>>(vertex, edges);
    k_scatterB<<<(NNZ * 16) / 256, 256>>>(vertex, edges, degE, degV, W_edge, out);
}

// round 4
// speedup vs baseline: 1.1573x; 1.1573x over previous
#include <cuda_runtime.h>
#include <cstdint>

#define N_NODES 100000
#define N_EDGES 20000
#define NNZ     1000000
#define IN_CH   128
#define OUT_DIM 64

#define NC      (N_EDGES + N_NODES)       // 120000 concatenated buckets
#define SCAN_B  1024
#define NBLK    ((NC + SCAN_B - 1) / SCAN_B)  // 118

// ---------------------------------------------------------------------------
// Device-global scratch (allocation-free per harness rules)
// ---------------------------------------------------------------------------
__device__ __align__(16) float g_Xl[(size_t)N_NODES * OUT_DIM];  // 25.6 MB
__device__ __align__(16) float g_Xe[(size_t)N_EDGES * OUT_DIM];  // 5.12 MB
__device__ int g_cnt[NC];
__device__ int g_offp[NC];       // per-block exclusive partials
__device__ int g_bsum[NBLK];
__device__ int g_boff[NBLK];
__device__ int g_off[NC + 1];    // global exclusive offsets
__device__ int g_cur[NC];        // fill cursors
__device__ int g_permA[NNZ];     // bucketed by edge -> stores vertex id
__device__ int g_permB[NNZ];     // bucketed by node -> stores edge id

// ---------------------------------------------------------------------------
// CSR build
// ---------------------------------------------------------------------------
__global__ void k_clear() {
    int t = blockIdx.x * blockDim.x + threadIdx.x;
    if (t < NC) g_cnt[t] = 0;
}

__global__ void k_hist(const int* __restrict__ vertex, const int* __restrict__ edges) {
    int i = blockIdx.x * blockDim.x + threadIdx.x;
    if (i >= NNZ) return;
    atomicAdd(&g_cnt[edges[i]], 1);
    atomicAdd(&g_cnt[N_EDGES + vertex[i]], 1);
}

__global__ __launch_bounds__(SCAN_B) void k_scan1() {
    __shared__ int s[SCAN_B];
    int t = threadIdx.x;
    int g = blockIdx.x * SCAN_B + t;
    int val = (g < NC) ? g_cnt[g] : 0;
    s[t] = val;
    __syncthreads();
    int incl = val;
    #pragma unroll
    for (int d = 1; d < SCAN_B; d <<= 1) {
        int x = (t >= d) ? s[t - d] : 0;
        __syncthreads();
        incl += x;
        s[t] = incl;
        __syncthreads();
    }
    if (g < NC) g_offp[g] = incl - val;
    if (t == SCAN_B - 1) g_bsum[blockIdx.x] = incl;
}

__global__ __launch_bounds__(128) void k_scan2() {
    __shared__ int s[128];
    int t = threadIdx.x;
    int val = (t < NBLK) ? g_bsum[t] : 0;
    s[t] = val;
    __syncthreads();
    int incl = val;
    #pragma unroll
    for (int d = 1; d < 128; d <<= 1) {
        int x = (t >= d) ? s[t - d] : 0;
        __syncthreads();
        incl += x;
        s[t] = incl;
        __syncthreads();
    }
    if (t < NBLK) g_boff[t] = incl - val;
}

__global__ void k_scan3() {
    int g = blockIdx.x * blockDim.x + threadIdx.x;
    if (g < NC) {
        int o = g_offp[g] + g_boff[g / SCAN_B];
        g_off[g] = o;
        g_cur[g] = o;
    }
    if (g == 0) g_off[NC] = 2 * NNZ;
}

__global__ void k_fill(const int* __restrict__ vertex, const int* __restrict__ edges) {
    int i = blockIdx.x * blockDim.x + threadIdx.x;
    if (i >= NNZ) return;
    int e = edges[i];
    int v = vertex[i];
    int pA = atomicAdd(&g_cur[e], 1);
    g_permA[pA] = v;
    int pB = atomicAdd(&g_cur[N_EDGES + v], 1);
    g_permB[pB - NNZ] = e;
}

// ---------------------------------------------------------------------------
// GEMM: g_Xl[N,64] = X[N,128] @ W[128,64]
// ---------------------------------------------------------------------------
__global__ __launch_bounds__(256) void k_gemm(const float* __restrict__ X,
                                              const float* __restrict__ W) {
    __shared__ float Ws[IN_CH][OUT_DIM];
    __shared__ float Xs[32][68];

    const int tid  = threadIdx.x;
    const int row0 = blockIdx.x * 64;

    {
        const float4* W4  = (const float4*)W;
        float4*       Ws4 = (float4*)&Ws[0][0];
        #pragma unroll
        for (int i = tid; i < IN_CH * OUT_DIM / 4; i += 256) Ws4[i] = W4[i];
    }

    const int tx = tid & 15;
    const int ty = tid >> 4;

    float acc[4][4];
    #pragma unroll
    for (int i = 0; i < 4; ++i)
        #pragma unroll
        for (int j = 0; j < 4; ++j) acc[i][j] = 0.0f;

    const int lr  = tid >> 3;
    const int lkf = tid & 7;

    for (int kc = 0; kc < 4; ++kc) {
        __syncthreads();
        #pragma unroll
        for (int j = 0; j < 2; ++j) {
            int r    = lr + 32 * j;
            int grow = row0 + r;
            float4 x = make_float4(0.f, 0.f, 0.f, 0.f);
            if (grow < N_NODES)
                x = *(const float4*)(X + (size_t)grow * IN_CH + kc * 32 + lkf * 4);
            Xs[lkf * 4 + 0][r] = x.x;
            Xs[lkf * 4 + 1][r] = x.y;
            Xs[lkf * 4 + 2][r] = x.z;
            Xs[lkf * 4 + 3][r] = x.w;
        }
        __syncthreads();

        #pragma unroll
        for (int k = 0; k < 32; ++k) {
            float4 a = *(const float4*)&Xs[k][4 * ty];
            float4 b = *(const float4*)&Ws[kc * 32 + k][4 * tx];
            acc[0][0] += a.x * b.x; acc[0][1] += a.x * b.y;
            acc[0][2] += a.x * b.z; acc[0][3] += a.x * b.w;
            acc[1][0] += a.y * b.x; acc[1][1] += a.y * b.y;
            acc[1][2] += a.y * b.z; acc[1][3] += a.y * b.w;
            acc[2][0] += a.z * b.x; acc[2][1] += a.z * b.y;
            acc[2][2] += a.z * b.z; acc[2][3] += a.z * b.w;
            acc[3][0] += a.w * b.x; acc[3][1] += a.w * b.y;
            acc[3][2] += a.w * b.z; acc[3][3] += a.w * b.w;
        }
    }

    #pragma unroll
    for (int i = 0; i < 4; ++i) {
        int grow = row0 + 4 * ty + i;
        if (grow < N_NODES) {
            float4 o = make_float4(acc[i][0], acc[i][1], acc[i][2], acc[i][3]);
            *(float4*)(g_Xl + (size_t)grow * OUT_DIM + 4 * tx) = o;
        }
    }
}

// ---------------------------------------------------------------------------
// Gather 1: Xe[e] = (sum over incidences of Xl[v]) * degE[e] * W_edge[e]
// 16 threads per edge, float4 lanes, register accumulation, single store.
// ---------------------------------------------------------------------------
__global__ __launch_bounds__(256) void k_gatherA(const float* __restrict__ degE,
                                                 const float* __restrict__ W_edge) {
    int t = blockIdx.x * blockDim.x + threadIdx.x;
    int e = t >> 4;
    if (e >= N_EDGES) return;
    int c = (t & 15) << 2;

    int beg = g_off[e];
    int end = g_off[e + 1];

    float4 acc = make_float4(0.f, 0.f, 0.f, 0.f);
    #pragma unroll 4
    for (int j = beg; j < end; ++j) {
        int v = __ldg(&g_permA[j]);
        float4 x = *(const float4*)(g_Xl + (size_t)v * OUT_DIM + c);
        acc.x += x.x; acc.y += x.y; acc.z += x.z; acc.w += x.w;
    }
    float s = degE[e] * W_edge[e];
    acc.x *= s; acc.y *= s; acc.z *= s; acc.w *= s;
    *(float4*)(g_Xe + (size_t)e * OUT_DIM + c) = acc;
}

// ---------------------------------------------------------------------------
// Gather 2: out[v] = (sum over incidences of Xe[e]) * degV[v]
// ---------------------------------------------------------------------------
__global__ __launch_bounds__(256) void k_gatherB(const float* __restrict__ degV,
                                                 float* __restrict__ out) {
    int t = blockIdx.x * blockDim.x + threadIdx.x;
    int v = t >> 4;
    if (v >= N_NODES) return;
    int c = (t & 15) << 2;

    int beg = g_off[N_EDGES + v] - NNZ;
    int end = g_off[N_EDGES + v + 1] - NNZ;

    float4 acc = make_float4(0.f, 0.f, 0.f, 0.f);
    #pragma unroll 4
    for (int j = beg; j < end; ++j) {
        int e = __ldg(&g_permB[j]);
        float4 x = *(const float4*)(g_Xe + (size_t)e * OUT_DIM + c);
        acc.x += x.x; acc.y += x.y; acc.z += x.z; acc.w += x.w;
    }
    float s = degV[v];
    acc.x *= s; acc.y *= s; acc.z *= s; acc.w *= s;
    *(float4*)(out + (size_t)v * OUT_DIM + c) = acc;
}

// ---------------------------------------------------------------------------
extern "C" void kernel_launch(void* const* d_in, const int* in_sizes, int n_in,
                              void* d_out, int out_size) {
    const float* X      = (const float*)d_in[0];
    const int*   vertex = (const int*)d_in[1];
    const int*   edges  = (const int*)d_in[2];
    const float* W_lin  = (const float*)d_in[3];
    const float* degE   = (const float*)d_in[4];
    const float* degV   = (const float*)d_in[5];
    const float* W_edge = (const float*)d_in[6];
    float*       out    = (float*)d_out;

    k_clear<<<(NC + 255) / 256, 256>>>();
    k_hist<<<(NNZ + 255) / 256, 256>>>(vertex, edges);
    k_scan1<<<NBLK, SCAN_B>>>();
    k_scan2<<<1, 128>>>();
    k_scan3<<<(NC + 255) / 256, 256>>>();
    k_fill<<<(NNZ + 255) / 256, 256>>>(vertex, edges);
    k_gemm<<<(N_NODES + 63) / 64, 256>>>(X, W_lin);
    k_gatherA<<<(N_EDGES * 16 + 255) / 256, 256>>>(degE, W_edge);
    k_gatherB<<<(N_NODES * 16 + 255) / 256, 256>>>(degV, out);
}